// round 7
// baseline (speedup 1.0000x reference)
#include <cuda_runtime.h>
#include <cstdint>

#define BB  32
#define SS  512
#define HH  768
#define TT  100
#define THH 512
#define LL  5

// Scratch (static __device__ — no allocation at launch time)
__device__ float g_z1[(size_t)BB * SS * HH];   // 48 MB: seq @ W1[l] + b1[l]
__device__ float g_parts[8 * BB * HH];         // per-chunk masked sums of relu(LN(z1))
__device__ float g_pooled[BB * HH];            // pooled @ W2[l] + b2[l]

// ---- packed fp32x2 FMA (sm_100+; SASS FFMA2, 2x fp32 throughput) -----------
__device__ __forceinline__ void fma2(unsigned long long& d,
                                     unsigned long long a,
                                     unsigned long long b) {
    asm("fma.rn.f32x2 %0, %1, %2, %0;" : "+l"(d) : "l"(a), "l"(b));
}
__device__ __forceinline__ unsigned long long pack2(float x) {
    unsigned long long r;
    asm("mov.b64 %0, {%1, %1};" : "=l"(r) : "f"(x));
    return r;
}
__device__ __forceinline__ float lo32(unsigned long long v) {
    return __uint_as_float((unsigned)(v & 0xffffffffull));
}
__device__ __forceinline__ float hi32(unsigned long long v) {
    return __uint_as_float((unsigned)(v >> 32));
}

// ---- GEMM1 helpers (fixed-buffer; called with compile-time buffer refs) ----
__device__ __forceinline__ void mma_ktile(
    const float (&Asb)[8][256], const float (&Bsb)[8][128],
    unsigned long long (&acc2)[8][4], int tx, int ty)
{
    #pragma unroll
    for (int k = 0; k < 8; k++) {
        // duplicated-A broadcast pairs: {a,a} per 64-bit half of each LDS.128
        ulonglong2 p0 = *(const ulonglong2*)&Asb[k][ty * 8];            // rows ty*4+0,1
        ulonglong2 p1 = *(const ulonglong2*)&Asb[k][ty * 8 + 4];        // rows ty*4+2,3
        ulonglong2 p2 = *(const ulonglong2*)&Asb[k][128 + ty * 8];      // rows 64+ty*4+0,1
        ulonglong2 p3 = *(const ulonglong2*)&Asb[k][128 + ty * 8 + 4];  // rows 64+ty*4+2,3
        // B column-pairs: two conflict-free LDS.128
        ulonglong2 q0 = *(const ulonglong2*)&Bsb[k][tx * 4];            // cols tx*4..+3
        ulonglong2 q1 = *(const ulonglong2*)&Bsb[k][tx * 4 + 64];       // cols tx*4+64..+67

        fma2(acc2[0][0], p0.x, q0.x); fma2(acc2[0][1], p0.x, q0.y);
        fma2(acc2[0][2], p0.x, q1.x); fma2(acc2[0][3], p0.x, q1.y);
        fma2(acc2[1][0], p0.y, q0.x); fma2(acc2[1][1], p0.y, q0.y);
        fma2(acc2[1][2], p0.y, q1.x); fma2(acc2[1][3], p0.y, q1.y);
        fma2(acc2[2][0], p1.x, q0.x); fma2(acc2[2][1], p1.x, q0.y);
        fma2(acc2[2][2], p1.x, q1.x); fma2(acc2[2][3], p1.x, q1.y);
        fma2(acc2[3][0], p1.y, q0.x); fma2(acc2[3][1], p1.y, q0.y);
        fma2(acc2[3][2], p1.y, q1.x); fma2(acc2[3][3], p1.y, q1.y);
        fma2(acc2[4][0], p2.x, q0.x); fma2(acc2[4][1], p2.x, q0.y);
        fma2(acc2[4][2], p2.x, q1.x); fma2(acc2[4][3], p2.x, q1.y);
        fma2(acc2[5][0], p2.y, q0.x); fma2(acc2[5][1], p2.y, q0.y);
        fma2(acc2[5][2], p2.y, q1.x); fma2(acc2[5][3], p2.y, q1.y);
        fma2(acc2[6][0], p3.x, q0.x); fma2(acc2[6][1], p3.x, q0.y);
        fma2(acc2[6][2], p3.x, q1.x); fma2(acc2[6][3], p3.x, q1.y);
        fma2(acc2[7][0], p3.y, q0.x); fma2(acc2[7][1], p3.y, q0.y);
        fma2(acc2[7][2], p3.y, q1.x); fma2(acc2[7][3], p3.y, q1.y);
    }
}

__device__ __forceinline__ void stage_tile(
    float (&Asb)[8][256], float (&Bsb)[8][128],
    const float4& a4, const float4& b4,
    int aRow, int aCol, int bRow, int bCol)
{
    *(unsigned long long*)&Asb[aCol + 0][2 * aRow] = pack2(a4.x);
    *(unsigned long long*)&Asb[aCol + 1][2 * aRow] = pack2(a4.y);
    *(unsigned long long*)&Asb[aCol + 2][2 * aRow] = pack2(a4.z);
    *(unsigned long long*)&Asb[aCol + 3][2 * aRow] = pack2(a4.w);
    *(float4*)&Bsb[bRow][bCol] = b4;
}

// ---------------------------------------------------------------------------
// K1: z1[b, s, d] = sum_h seq[b,s,h] * W1[l(b),h,d] + b1[l(b),d]
// 128x128x8 tiles, double-buffered smem (kt-loop unrolled x2 manually so
// buffer addresses are compile-time; further compiler unrolling capped to
// bound the I$ footprint), 8 rows x 4 f32x2 column-pairs per thread.
// A tile stored DUPLICATED in smem; B pairs via conflict-free LDS.128.
// grid = (HH/128=6, SS/128=4, BB=32)
// ---------------------------------------------------------------------------
__global__ __launch_bounds__(256, 2) void gemm1_kernel(
    const float* __restrict__ seq, const float* __restrict__ W1,
    const float* __restrict__ b1, const int* __restrict__ lang)
{
    __shared__ float As0[8][256], As1[8][256];   // [k][2*m] duplicated pairs
    __shared__ float Bs0[8][128], Bs1[8][128];   // [k][n]

    const int b = blockIdx.z;
    const int l = lang[b];
    const int tid = threadIdx.x;

    const int aRow = tid >> 1;            // 0..127
    const int aCol = (tid & 1) << 2;      // 0 or 4
    const int bRow = tid >> 5;            // 0..7
    const int bCol = (tid & 31) << 2;     // 0..124

    const float* Aptr = seq + ((size_t)b * SS + blockIdx.y * 128 + aRow) * HH + aCol;
    const float* Bptr = W1 + (size_t)l * HH * HH + (size_t)bRow * HH
                        + blockIdx.x * 128 + bCol;

    // Prologue: stage tile 0 into buffer 0
    stage_tile(As0, Bs0, *(const float4*)Aptr, *(const float4*)Bptr,
               aRow, aCol, bRow, bCol);
    __syncthreads();

    unsigned long long acc2[8][4] = {};
    const int tx = tid & 15;   // col group
    const int ty = tid >> 4;   // row group

    const int NKT = HH / 8;    // 96 (even)
    #pragma unroll 1
    for (int kt = 0; kt < NKT; kt += 2) {
        // ---- phase A: compute buf0 (tile kt), stage tile kt+1 -> buf1 ----
        {
            float4 na4 = *(const float4*)(Aptr + (kt + 1) * 8);
            float4 nb4 = *(const float4*)(Bptr + (size_t)(kt + 1) * 8 * HH);
            mma_ktile(As0, Bs0, acc2, tx, ty);
            stage_tile(As1, Bs1, na4, nb4, aRow, aCol, bRow, bCol);
        }
        __syncthreads();

        // ---- phase B: compute buf1 (tile kt+1), stage tile kt+2 -> buf0 ----
        {
            float4 na4, nb4;
            const bool more = (kt + 2) < NKT;
            if (more) {
                na4 = *(const float4*)(Aptr + (kt + 2) * 8);
                nb4 = *(const float4*)(Bptr + (size_t)(kt + 2) * 8 * HH);
            }
            mma_ktile(As1, Bs1, acc2, tx, ty);
            if (more)
                stage_tile(As0, Bs0, na4, nb4, aRow, aCol, bRow, bCol);
        }
        __syncthreads();
    }

    // Epilogue: + bias, store
    const int d0 = blockIdx.x * 128;
    const float* bias = b1 + l * HH + d0;
    float4 bv0 = *(const float4*)(bias + tx * 4);
    float4 bv1 = *(const float4*)(bias + tx * 4 + 64);
    float* C = g_z1 + ((size_t)b * SS + blockIdx.y * 128) * HH + d0;

    #pragma unroll
    for (int i = 0; i < 8; i++) {
        int m = (i < 4) ? (ty * 4 + i) : (64 + ty * 4 + (i - 4));
        float4 o0, o1;
        o0.x = lo32(acc2[i][0]) + bv0.x;
        o0.y = hi32(acc2[i][0]) + bv0.y;
        o0.z = lo32(acc2[i][1]) + bv0.z;
        o0.w = hi32(acc2[i][1]) + bv0.w;
        o1.x = lo32(acc2[i][2]) + bv1.x;
        o1.y = hi32(acc2[i][2]) + bv1.y;
        o1.z = lo32(acc2[i][3]) + bv1.z;
        o1.w = hi32(acc2[i][3]) + bv1.w;
        *(float4*)(C + (size_t)m * HH + tx * 4)      = o0;
        *(float4*)(C + (size_t)m * HH + tx * 4 + 64) = o1;
    }
}

// ---------------------------------------------------------------------------
// K2: per row of z1: LayerNorm(g1,be1) -> ReLU -> * mask, summed over rows of
// a 64-row chunk, partial written to g_parts[chunk][b][:].
// grid = (8 chunks, BB), 256 threads (8 warps, 1 warp = 1 row at a time).
// Vectorized: each lane owns cols lane*4+128*j .. +3, j in 0..5 (LDG.128).
// ---------------------------------------------------------------------------
__global__ __launch_bounds__(256) void ln_pool_kernel(
    const float* __restrict__ gam, const float* __restrict__ bet,
    const int* __restrict__ lang, const float* __restrict__ mask)
{
    const int b = blockIdx.y, chunk = blockIdx.x;
    const int l = lang[b];
    const int warp = threadIdx.x >> 5, lane = threadIdx.x & 31;

    float4 gv[6], bev[6], accp[6];
    #pragma unroll
    for (int j = 0; j < 6; j++) {
        int c = lane * 4 + 128 * j;
        gv[j]  = *(const float4*)&gam[l * HH + c];
        bev[j] = *(const float4*)&bet[l * HH + c];
        accp[j] = make_float4(0.f, 0.f, 0.f, 0.f);
    }

    for (int i = 0; i < 8; i++) {
        int r = chunk * 64 + warp * 8 + i;
        const float* row = g_z1 + ((size_t)b * SS + r) * HH;
        float4 v[6];
        float s1 = 0.f, s2 = 0.f;
        #pragma unroll
        for (int j = 0; j < 6; j++) {
            float4 x = *(const float4*)&row[lane * 4 + 128 * j];
            v[j] = x;
            s1 += x.x + x.y + x.z + x.w;
            s2 += x.x * x.x + x.y * x.y + x.z * x.z + x.w * x.w;
        }
        #pragma unroll
        for (int o = 16; o > 0; o >>= 1) {
            s1 += __shfl_xor_sync(0xffffffffu, s1, o);
            s2 += __shfl_xor_sync(0xffffffffu, s2, o);
        }
        float mean = s1 * (1.0f / HH);
        float var  = s2 * (1.0f / HH) - mean * mean;
        float inv  = rsqrtf(var + 1e-5f);
        float mwt  = mask[b * SS + r];
        #pragma unroll
        for (int j = 0; j < 6; j++) {
            accp[j].x += mwt * fmaxf((v[j].x - mean) * inv * gv[j].x + bev[j].x, 0.f);
            accp[j].y += mwt * fmaxf((v[j].y - mean) * inv * gv[j].y + bev[j].y, 0.f);
            accp[j].z += mwt * fmaxf((v[j].z - mean) * inv * gv[j].z + bev[j].z, 0.f);
            accp[j].w += mwt * fmaxf((v[j].w - mean) * inv * gv[j].w + bev[j].w, 0.f);
        }
    }

    __shared__ float sm[8][HH];
    #pragma unroll
    for (int j = 0; j < 6; j++)
        *(float4*)&sm[warp][lane * 4 + 128 * j] = accp[j];
    __syncthreads();
    for (int c = threadIdx.x; c < HH; c += 256) {
        float s = 0.f;
        #pragma unroll
        for (int w = 0; w < 8; w++) s += sm[w][c];
        g_parts[((size_t)chunk * BB + b) * HH + c] = s;
    }
}

// ---------------------------------------------------------------------------
// K3: pooled[b,d] = (masked_sum_h1[b,:]/denom) @ W2[l] + b2[l,d]*(msum/denom)
// grid = (3, BB), 256 threads; each thread owns one output column d.
// ---------------------------------------------------------------------------
__global__ __launch_bounds__(256) void gemm2_kernel(
    const float* __restrict__ mask, const int* __restrict__ lang,
    const float* __restrict__ W2, const float* __restrict__ b2)
{
    const int b = blockIdx.y;
    const int l = lang[b];
    __shared__ float ph[HH];
    __shared__ float sred[8];
    __shared__ float sden;

    float ms = 0.f;
    for (int s = threadIdx.x; s < SS; s += 256) ms += mask[b * SS + s];
    #pragma unroll
    for (int o = 16; o > 0; o >>= 1) ms += __shfl_xor_sync(0xffffffffu, ms, o);
    if ((threadIdx.x & 31) == 0) sred[threadIdx.x >> 5] = ms;
    __syncthreads();
    if (threadIdx.x == 0) {
        float t = 0.f;
        #pragma unroll
        for (int w = 0; w < 8; w++) t += sred[w];
        sden = t;
    }
    __syncthreads();
    const float msum = sden;
    const float invd = 1.0f / (msum + 1e-10f);

    for (int c = threadIdx.x; c < HH; c += 256) {
        float s = 0.f;
        #pragma unroll
        for (int ch = 0; ch < 8; ch++)
            s += g_parts[((size_t)ch * BB + b) * HH + c];
        ph[c] = s * invd;
    }
    __syncthreads();

    const int d = blockIdx.x * 256 + threadIdx.x;
    const float* W = W2 + (size_t)l * HH * HH + d;
    float acc = 0.f;
    #pragma unroll 8
    for (int h = 0; h < HH; h++) acc += ph[h] * W[(size_t)h * HH];
    g_pooled[b * HH + d] = acc + b2[l * HH + d] * (msum * invd);
}

// ---------------------------------------------------------------------------
// K4: combined = [pooled | lda]; fused = LN(combined @ Wf + bf; gf, bef); ReLU
// grid = BB blocks, 512 threads (one thread per output column).
// ---------------------------------------------------------------------------
__global__ __launch_bounds__(512) void fuse_kernel(
    const float* __restrict__ lda, const float* __restrict__ Wf,
    const float* __restrict__ bf, const float* __restrict__ gf,
    const float* __restrict__ bef, float* __restrict__ out)
{
    const int b = blockIdx.x, d = threadIdx.x;
    __shared__ float comb[HH + TT];
    __shared__ float sr1[16], sr2[16];

    for (int i = d; i < HH; i += 512) comb[i] = g_pooled[b * HH + i];
    for (int i = d; i < TT; i += 512) comb[HH + i] = lda[b * TT + i];
    __syncthreads();

    float acc = bf[d];
    #pragma unroll 4
    for (int i = 0; i < HH + TT; i++) acc += comb[i] * Wf[(size_t)i * THH + d];

    // block-wide LN over the 512 outputs
    float s1 = acc, s2 = acc * acc;
    #pragma unroll
    for (int o = 16; o > 0; o >>= 1) {
        s1 += __shfl_xor_sync(0xffffffffu, s1, o);
        s2 += __shfl_xor_sync(0xffffffffu, s2, o);
    }
    const int warp = d >> 5, lane = d & 31;
    if (lane == 0) { sr1[warp] = s1; sr2[warp] = s2; }
    __syncthreads();
    if (warp == 0) {
        float t1 = (lane < 16) ? sr1[lane] : 0.f;
        float t2 = (lane < 16) ? sr2[lane] : 0.f;
        #pragma unroll
        for (int o = 16; o > 0; o >>= 1) {
            t1 += __shfl_xor_sync(0xffffffffu, t1, o);
            t2 += __shfl_xor_sync(0xffffffffu, t2, o);
        }
        if (lane == 0) { sr1[0] = t1; sr2[0] = t2; }
    }
    __syncthreads();
    float mean = sr1[0] * (1.0f / THH);
    float var  = sr2[0] * (1.0f / THH) - mean * mean;
    float inv  = rsqrtf(var + 1e-5f);
    float t = (acc - mean) * inv * gf[d] + bef[d];
    out[b * THH + d] = fmaxf(t, 0.f);
}

// ---------------------------------------------------------------------------
extern "C" void kernel_launch(void* const* d_in, const int* in_sizes, int n_in,
                              void* d_out, int out_size)
{
    const float* seq  = (const float*)d_in[0];
    const float* mask = (const float*)d_in[1];
    const int*   lang = (const int*)  d_in[2];
    const float* lda  = (const float*)d_in[3];
    const float* W1   = (const float*)d_in[4];
    const float* b1   = (const float*)d_in[5];
    const float* gam1 = (const float*)d_in[6];
    const float* bet1 = (const float*)d_in[7];
    const float* W2   = (const float*)d_in[8];
    const float* b2   = (const float*)d_in[9];
    const float* Wf   = (const float*)d_in[10];
    const float* bfv  = (const float*)d_in[11];
    const float* gfv  = (const float*)d_in[12];
    const float* befv = (const float*)d_in[13];
    float* out = (float*)d_out;

    dim3 grid1(HH / 128, SS / 128, BB);      // (6, 4, 32)
    gemm1_kernel<<<grid1, 256>>>(seq, W1, b1, lang);

    dim3 grid2(8, BB);
    ln_pool_kernel<<<grid2, 256>>>(gam1, bet1, lang, mask);

    dim3 grid3(HH / 256, BB);                // (3, 32)
    gemm2_kernel<<<grid3, 256>>>(mask, lang, W2, b2);

    fuse_kernel<<<BB, 512>>>(lda, Wf, bfv, gfv, befv, out);
}

// round 14
// speedup vs baseline: 1.0977x; 1.0977x over previous
#include <cuda_runtime.h>
#include <cstdint>

#define BB  32
#define SS  512
#define HH  768
#define TT  100
#define THH 512
#define LL  5

// Scratch (static __device__ — no allocation at launch time)
__device__ float g_z1[(size_t)BB * SS * HH];   // 48 MB: seq @ W1[l] + b1[l]
__device__ float g_parts[8 * BB * HH];         // per-chunk masked sums of relu(LN(z1))
__device__ float g_pooled[BB * HH];            // pooled @ W2[l] + b2[l]

// ---- packed fp32x2 FMA (sm_100+; SASS FFMA2, 2x fp32 throughput) -----------
__device__ __forceinline__ void fma2(unsigned long long& d,
                                     unsigned long long a,
                                     unsigned long long b) {
    asm("fma.rn.f32x2 %0, %1, %2, %0;" : "+l"(d) : "l"(a), "l"(b));
}
__device__ __forceinline__ unsigned long long pack2(float x) {
    unsigned long long r;
    asm("mov.b64 %0, {%1, %1};" : "=l"(r) : "f"(x));
    return r;
}
__device__ __forceinline__ float lo32(unsigned long long v) {
    return __uint_as_float((unsigned)(v & 0xffffffffull));
}
__device__ __forceinline__ float hi32(unsigned long long v) {
    return __uint_as_float((unsigned)(v >> 32));
}

// ---- GEMM1 helpers (fixed-buffer; called with compile-time buffer refs) ----
__device__ __forceinline__ void mma_ktile(
    const float (&Asb)[8][256], const float (&Bsb)[8][128],
    unsigned long long (&acc2)[8][4], int tx, int ty)
{
    #pragma unroll
    for (int k = 0; k < 8; k++) {
        // duplicated-A broadcast pairs: {a,a} per 64-bit half of each LDS.128
        ulonglong2 p0 = *(const ulonglong2*)&Asb[k][ty * 8];            // rows ty*4+0,1
        ulonglong2 p1 = *(const ulonglong2*)&Asb[k][ty * 8 + 4];        // rows ty*4+2,3
        ulonglong2 p2 = *(const ulonglong2*)&Asb[k][128 + ty * 8];      // rows 64+ty*4+0,1
        ulonglong2 p3 = *(const ulonglong2*)&Asb[k][128 + ty * 8 + 4];  // rows 64+ty*4+2,3
        // B column-pairs: two conflict-free LDS.128
        ulonglong2 q0 = *(const ulonglong2*)&Bsb[k][tx * 4];            // cols tx*4..+3
        ulonglong2 q1 = *(const ulonglong2*)&Bsb[k][tx * 4 + 64];       // cols tx*4+64..+67

        fma2(acc2[0][0], p0.x, q0.x); fma2(acc2[0][1], p0.x, q0.y);
        fma2(acc2[0][2], p0.x, q1.x); fma2(acc2[0][3], p0.x, q1.y);
        fma2(acc2[1][0], p0.y, q0.x); fma2(acc2[1][1], p0.y, q0.y);
        fma2(acc2[1][2], p0.y, q1.x); fma2(acc2[1][3], p0.y, q1.y);
        fma2(acc2[2][0], p1.x, q0.x); fma2(acc2[2][1], p1.x, q0.y);
        fma2(acc2[2][2], p1.x, q1.x); fma2(acc2[2][3], p1.x, q1.y);
        fma2(acc2[3][0], p1.y, q0.x); fma2(acc2[3][1], p1.y, q0.y);
        fma2(acc2[3][2], p1.y, q1.x); fma2(acc2[3][3], p1.y, q1.y);
        fma2(acc2[4][0], p2.x, q0.x); fma2(acc2[4][1], p2.x, q0.y);
        fma2(acc2[4][2], p2.x, q1.x); fma2(acc2[4][3], p2.x, q1.y);
        fma2(acc2[5][0], p2.y, q0.x); fma2(acc2[5][1], p2.y, q0.y);
        fma2(acc2[5][2], p2.y, q1.x); fma2(acc2[5][3], p2.y, q1.y);
        fma2(acc2[6][0], p3.x, q0.x); fma2(acc2[6][1], p3.x, q0.y);
        fma2(acc2[6][2], p3.x, q1.x); fma2(acc2[6][3], p3.x, q1.y);
        fma2(acc2[7][0], p3.y, q0.x); fma2(acc2[7][1], p3.y, q0.y);
        fma2(acc2[7][2], p3.y, q1.x); fma2(acc2[7][3], p3.y, q1.y);
    }
}

__device__ __forceinline__ void stage_tile(
    float (&Asb)[8][256], float (&Bsb)[8][128],
    const float4& a4, const float4& b4,
    int aRow, int aCol, int bRow, int bCol)
{
    *(unsigned long long*)&Asb[aCol + 0][2 * aRow] = pack2(a4.x);
    *(unsigned long long*)&Asb[aCol + 1][2 * aRow] = pack2(a4.y);
    *(unsigned long long*)&Asb[aCol + 2][2 * aRow] = pack2(a4.z);
    *(unsigned long long*)&Asb[aCol + 3][2 * aRow] = pack2(a4.w);
    *(float4*)&Bsb[bRow][bCol] = b4;
}

// ---------------------------------------------------------------------------
// K1: z1[b, s, d] = sum_h seq[b,s,h] * W1[l(b),h,d] + b1[l(b),d]
// 128x128x8 tiles, double-buffered smem, FFMA2 inner loop.
// grid = (HH/128=6, SS/128=4, BB=32)
// ---------------------------------------------------------------------------
__global__ __launch_bounds__(256, 2) void gemm1_kernel(
    const float* __restrict__ seq, const float* __restrict__ W1,
    const float* __restrict__ b1, const int* __restrict__ lang)
{
    __shared__ float As0[8][256], As1[8][256];   // [k][2*m] duplicated pairs
    __shared__ float Bs0[8][128], Bs1[8][128];   // [k][n]

    const int b = blockIdx.z;
    const int l = lang[b];
    const int tid = threadIdx.x;

    const int aRow = tid >> 1;            // 0..127
    const int aCol = (tid & 1) << 2;      // 0 or 4
    const int bRow = tid >> 5;            // 0..7
    const int bCol = (tid & 31) << 2;     // 0..124

    const float* Aptr = seq + ((size_t)b * SS + blockIdx.y * 128 + aRow) * HH + aCol;
    const float* Bptr = W1 + (size_t)l * HH * HH + (size_t)bRow * HH
                        + blockIdx.x * 128 + bCol;

    stage_tile(As0, Bs0, *(const float4*)Aptr, *(const float4*)Bptr,
               aRow, aCol, bRow, bCol);
    __syncthreads();

    unsigned long long acc2[8][4] = {};
    const int tx = tid & 15;   // col group
    const int ty = tid >> 4;   // row group

    const int NKT = HH / 8;    // 96 (even)
    #pragma unroll 1
    for (int kt = 0; kt < NKT; kt += 2) {
        {
            float4 na4 = *(const float4*)(Aptr + (kt + 1) * 8);
            float4 nb4 = *(const float4*)(Bptr + (size_t)(kt + 1) * 8 * HH);
            mma_ktile(As0, Bs0, acc2, tx, ty);
            stage_tile(As1, Bs1, na4, nb4, aRow, aCol, bRow, bCol);
        }
        __syncthreads();
        {
            float4 na4, nb4;
            const bool more = (kt + 2) < NKT;
            if (more) {
                na4 = *(const float4*)(Aptr + (kt + 2) * 8);
                nb4 = *(const float4*)(Bptr + (size_t)(kt + 2) * 8 * HH);
            }
            mma_ktile(As1, Bs1, acc2, tx, ty);
            if (more)
                stage_tile(As0, Bs0, na4, nb4, aRow, aCol, bRow, bCol);
        }
        __syncthreads();
    }

    const int d0 = blockIdx.x * 128;
    const float* bias = b1 + l * HH + d0;
    float4 bv0 = *(const float4*)(bias + tx * 4);
    float4 bv1 = *(const float4*)(bias + tx * 4 + 64);
    float* C = g_z1 + ((size_t)b * SS + blockIdx.y * 128) * HH + d0;

    #pragma unroll
    for (int i = 0; i < 8; i++) {
        int m = (i < 4) ? (ty * 4 + i) : (64 + ty * 4 + (i - 4));
        float4 o0, o1;
        o0.x = lo32(acc2[i][0]) + bv0.x;
        o0.y = hi32(acc2[i][0]) + bv0.y;
        o0.z = lo32(acc2[i][1]) + bv0.z;
        o0.w = hi32(acc2[i][1]) + bv0.w;
        o1.x = lo32(acc2[i][2]) + bv1.x;
        o1.y = hi32(acc2[i][2]) + bv1.y;
        o1.z = lo32(acc2[i][3]) + bv1.z;
        o1.w = hi32(acc2[i][3]) + bv1.w;
        *(float4*)(C + (size_t)m * HH + tx * 4)      = o0;
        *(float4*)(C + (size_t)m * HH + tx * 4 + 64) = o1;
    }
}

// ---------------------------------------------------------------------------
// K2: LN+ReLU+masked-sum over 64-row chunks.
// grid = (8, BB), 256 threads.
// ---------------------------------------------------------------------------
__global__ __launch_bounds__(256) void ln_pool_kernel(
    const float* __restrict__ gam, const float* __restrict__ bet,
    const int* __restrict__ lang, const float* __restrict__ mask)
{
    const int b = blockIdx.y, chunk = blockIdx.x;
    const int l = lang[b];
    const int warp = threadIdx.x >> 5, lane = threadIdx.x & 31;

    float4 gv[6], bev[6], accp[6];
    #pragma unroll
    for (int j = 0; j < 6; j++) {
        int c = lane * 4 + 128 * j;
        gv[j]  = *(const float4*)&gam[l * HH + c];
        bev[j] = *(const float4*)&bet[l * HH + c];
        accp[j] = make_float4(0.f, 0.f, 0.f, 0.f);
    }

    for (int i = 0; i < 8; i++) {
        int r = chunk * 64 + warp * 8 + i;
        const float* row = g_z1 + ((size_t)b * SS + r) * HH;
        float4 v[6];
        float s1 = 0.f, s2 = 0.f;
        #pragma unroll
        for (int j = 0; j < 6; j++) {
            float4 x = *(const float4*)&row[lane * 4 + 128 * j];
            v[j] = x;
            s1 += x.x + x.y + x.z + x.w;
            s2 += x.x * x.x + x.y * x.y + x.z * x.z + x.w * x.w;
        }
        #pragma unroll
        for (int o = 16; o > 0; o >>= 1) {
            s1 += __shfl_xor_sync(0xffffffffu, s1, o);
            s2 += __shfl_xor_sync(0xffffffffu, s2, o);
        }
        float mean = s1 * (1.0f / HH);
        float var  = s2 * (1.0f / HH) - mean * mean;
        float inv  = rsqrtf(var + 1e-5f);
        float mwt  = mask[b * SS + r];
        #pragma unroll
        for (int j = 0; j < 6; j++) {
            accp[j].x += mwt * fmaxf((v[j].x - mean) * inv * gv[j].x + bev[j].x, 0.f);
            accp[j].y += mwt * fmaxf((v[j].y - mean) * inv * gv[j].y + bev[j].y, 0.f);
            accp[j].z += mwt * fmaxf((v[j].z - mean) * inv * gv[j].z + bev[j].z, 0.f);
            accp[j].w += mwt * fmaxf((v[j].w - mean) * inv * gv[j].w + bev[j].w, 0.f);
        }
    }

    __shared__ float sm[8][HH];
    #pragma unroll
    for (int j = 0; j < 6; j++)
        *(float4*)&sm[warp][lane * 4 + 128 * j] = accp[j];
    __syncthreads();
    for (int c = threadIdx.x; c < HH; c += 256) {
        float s = 0.f;
        #pragma unroll
        for (int w = 0; w < 8; w++) s += sm[w][c];
        g_parts[((size_t)chunk * BB + b) * HH + c] = s;
    }
}

// ---------------------------------------------------------------------------
// K3: pooled[b,d] = (masked_sum_h1[b,:]/denom) @ W2[l] + b2[l,d]*(msum/denom)
// grid = (3, BB), 256 threads. 8 independent accumulators + register
// double-buffered prefetch (MLP=8); __ldg on the strided weight loads.
// ---------------------------------------------------------------------------
__global__ __launch_bounds__(256) void gemm2_kernel(
    const float* __restrict__ mask, const int* __restrict__ lang,
    const float* __restrict__ W2, const float* __restrict__ b2)
{
    const int b = blockIdx.y;
    const int l = lang[b];
    __shared__ float ph[HH];
    __shared__ float sred[8];
    __shared__ float sden;

    float ms = 0.f;
    for (int s = threadIdx.x; s < SS; s += 256) ms += mask[b * SS + s];
    #pragma unroll
    for (int o = 16; o > 0; o >>= 1) ms += __shfl_xor_sync(0xffffffffu, ms, o);
    if ((threadIdx.x & 31) == 0) sred[threadIdx.x >> 5] = ms;
    __syncthreads();
    if (threadIdx.x == 0) {
        float t = 0.f;
        #pragma unroll
        for (int w = 0; w < 8; w++) t += sred[w];
        sden = t;
    }
    __syncthreads();
    const float msum = sden;
    const float invd = 1.0f / (msum + 1e-10f);

    for (int c = threadIdx.x; c < HH; c += 256) {
        float s = 0.f;
        #pragma unroll
        for (int ch = 0; ch < 8; ch++)
            s += g_parts[((size_t)ch * BB + b) * HH + c];
        ph[c] = s * invd;
    }
    __syncthreads();

    const int d = blockIdx.x * 256 + threadIdx.x;
    const float* W = W2 + (size_t)l * HH * HH + d;

    float acc[8];
    float w[8], wn[8];
    #pragma unroll
    for (int u = 0; u < 8; u++) { acc[u] = 0.f; w[u] = __ldg(&W[(size_t)u * HH]); }

    // HH = 768; batches at h0 = 0..760 step 8; prefetch valid while h0 <= 752.
    #pragma unroll 1
    for (int h0 = 0; h0 <= 752; h0 += 8) {
        #pragma unroll
        for (int u = 0; u < 8; u++) wn[u] = __ldg(&W[(size_t)(h0 + 8 + u) * HH]);
        #pragma unroll
        for (int u = 0; u < 8; u++) acc[u] += ph[h0 + u] * w[u];
        #pragma unroll
        for (int u = 0; u < 8; u++) w[u] = wn[u];
    }
    // final batch h0 = 760
    #pragma unroll
    for (int u = 0; u < 8; u++) acc[u] += ph[760 + u] * w[u];

    float total = ((acc[0] + acc[1]) + (acc[2] + acc[3]))
                + ((acc[4] + acc[5]) + (acc[6] + acc[7]));
    g_pooled[b * HH + d] = total + b2[l * HH + d] * (msum * invd);
}

// ---------------------------------------------------------------------------
// K4: combined = [pooled | lda]; fused = LN(combined @ Wf + bf; gf, bef); ReLU
// grid = BB blocks, 512 threads. 8 independent accumulators + register
// double-buffered prefetch (MLP=8); __ldg on the strided weight loads.
// ---------------------------------------------------------------------------
__global__ __launch_bounds__(512) void fuse_kernel(
    const float* __restrict__ lda, const float* __restrict__ Wf,
    const float* __restrict__ bf, const float* __restrict__ gf,
    const float* __restrict__ bef, float* __restrict__ out)
{
    const int b = blockIdx.x, d = threadIdx.x;
    __shared__ float comb[HH + TT];
    __shared__ float sr1[16], sr2[16];

    for (int i = d; i < HH; i += 512) comb[i] = g_pooled[b * HH + i];
    for (int i = d; i < TT; i += 512) comb[HH + i] = lda[b * TT + i];
    __syncthreads();

    const float* Wcol = Wf + d;   // element i at Wcol[i*THH]

    float acc[8];
    float w[8], wn[8];
    #pragma unroll
    for (int u = 0; u < 8; u++) { acc[u] = 0.f; w[u] = __ldg(&Wcol[(size_t)u * THH]); }

    // HH+TT = 868 = 8*108 + 4. Full batches at i0 = 0..856 step 8;
    // prefetch valid while i0 <= 848.
    #pragma unroll 1
    for (int i0 = 0; i0 <= 848; i0 += 8) {
        #pragma unroll
        for (int u = 0; u < 8; u++) wn[u] = __ldg(&Wcol[(size_t)(i0 + 8 + u) * THH]);
        #pragma unroll
        for (int u = 0; u < 8; u++) acc[u] += comb[i0 + u] * w[u];
        #pragma unroll
        for (int u = 0; u < 8; u++) w[u] = wn[u];
    }
    // final full batch i0 = 856
    #pragma unroll
    for (int u = 0; u < 8; u++) acc[u] += comb[856 + u] * w[u];
    // tail: i = 864..867
    #pragma unroll
    for (int u = 0; u < 4; u++) acc[u] += comb[864 + u] * __ldg(&Wcol[(size_t)(864 + u) * THH]);

    float accf = bf[d]
               + ((acc[0] + acc[1]) + (acc[2] + acc[3]))
               + ((acc[4] + acc[5]) + (acc[6] + acc[7]));

    // block-wide LN over the 512 outputs
    float s1 = accf, s2 = accf * accf;
    #pragma unroll
    for (int o = 16; o > 0; o >>= 1) {
        s1 += __shfl_xor_sync(0xffffffffu, s1, o);
        s2 += __shfl_xor_sync(0xffffffffu, s2, o);
    }
    const int warp = d >> 5, lane = d & 31;
    if (lane == 0) { sr1[warp] = s1; sr2[warp] = s2; }
    __syncthreads();
    if (warp == 0) {
        float t1 = (lane < 16) ? sr1[lane] : 0.f;
        float t2 = (lane < 16) ? sr2[lane] : 0.f;
        #pragma unroll
        for (int o = 16; o > 0; o >>= 1) {
            t1 += __shfl_xor_sync(0xffffffffu, t1, o);
            t2 += __shfl_xor_sync(0xffffffffu, t2, o);
        }
        if (lane == 0) { sr1[0] = t1; sr2[0] = t2; }
    }
    __syncthreads();
    float mean = sr1[0] * (1.0f / THH);
    float var  = sr2[0] * (1.0f / THH) - mean * mean;
    float inv  = rsqrtf(var + 1e-5f);
    float t = (accf - mean) * inv * gf[d] + bef[d];
    out[b * THH + d] = fmaxf(t, 0.f);
}

// ---------------------------------------------------------------------------
extern "C" void kernel_launch(void* const* d_in, const int* in_sizes, int n_in,
                              void* d_out, int out_size)
{
    const float* seq  = (const float*)d_in[0];
    const float* mask = (const float*)d_in[1];
    const int*   lang = (const int*)  d_in[2];
    const float* lda  = (const float*)d_in[3];
    const float* W1   = (const float*)d_in[4];
    const float* b1   = (const float*)d_in[5];
    const float* gam1 = (const float*)d_in[6];
    const float* bet1 = (const float*)d_in[7];
    const float* W2   = (const float*)d_in[8];
    const float* b2   = (const float*)d_in[9];
    const float* Wf   = (const float*)d_in[10];
    const float* bfv  = (const float*)d_in[11];
    const float* gfv  = (const float*)d_in[12];
    const float* befv = (const float*)d_in[13];
    float* out = (float*)d_out;

    dim3 grid1(HH / 128, SS / 128, BB);      // (6, 4, 32)
    gemm1_kernel<<<grid1, 256>>>(seq, W1, b1, lang);

    dim3 grid2(8, BB);
    ln_pool_kernel<<<grid2, 256>>>(gam1, bet1, lang, mask);

    dim3 grid3(HH / 256, BB);                // (3, 32)
    gemm2_kernel<<<grid3, 256>>>(mask, lang, W2, b2);

    fuse_kernel<<<BB, 512>>>(lda, Wf, bfv, gfv, befv, out);
}

// round 16
// speedup vs baseline: 1.3059x; 1.1896x over previous
#include <cuda_runtime.h>
#include <cstdint>

#define BB  32
#define SS  512
#define HH  768
#define TT  100
#define THH 512
#define LL  5

// Scratch (static __device__ — no allocation at launch time)
__device__ float g_z1[(size_t)BB * SS * HH];   // 48 MB: seq @ W1[l] + b1[l]
__device__ float g_parts[8 * BB * HH];         // per-chunk masked sums of relu(LN(z1))
__device__ float g_pooled[BB * HH];            // pooled @ W2[l] + b2[l]*msfac
__device__ float g_ph[BB * HH];                // masked-mean-pooled h1
__device__ float g_msfac[BB];                  // msum/(msum+eps)
__device__ float g_p2[6 * BB * HH];            // gemm2 row-chunk partials
__device__ float g_fp[7 * BB * THH];           // fuse  row-chunk partials

// ---- packed fp32x2 FMA (sm_100+; SASS FFMA2, 2x fp32 throughput) -----------
__device__ __forceinline__ void fma2(unsigned long long& d,
                                     unsigned long long a,
                                     unsigned long long b) {
    asm("fma.rn.f32x2 %0, %1, %2, %0;" : "+l"(d) : "l"(a), "l"(b));
}
__device__ __forceinline__ unsigned long long pack2(float x) {
    unsigned long long r;
    asm("mov.b64 %0, {%1, %1};" : "=l"(r) : "f"(x));
    return r;
}
__device__ __forceinline__ float lo32(unsigned long long v) {
    return __uint_as_float((unsigned)(v & 0xffffffffull));
}
__device__ __forceinline__ float hi32(unsigned long long v) {
    return __uint_as_float((unsigned)(v >> 32));
}

// ---- GEMM1 helpers (fixed-buffer; called with compile-time buffer refs) ----
__device__ __forceinline__ void mma_ktile(
    const float (&Asb)[8][256], const float (&Bsb)[8][128],
    unsigned long long (&acc2)[8][4], int tx, int ty)
{
    #pragma unroll
    for (int k = 0; k < 8; k++) {
        ulonglong2 p0 = *(const ulonglong2*)&Asb[k][ty * 8];
        ulonglong2 p1 = *(const ulonglong2*)&Asb[k][ty * 8 + 4];
        ulonglong2 p2 = *(const ulonglong2*)&Asb[k][128 + ty * 8];
        ulonglong2 p3 = *(const ulonglong2*)&Asb[k][128 + ty * 8 + 4];
        ulonglong2 q0 = *(const ulonglong2*)&Bsb[k][tx * 4];
        ulonglong2 q1 = *(const ulonglong2*)&Bsb[k][tx * 4 + 64];

        fma2(acc2[0][0], p0.x, q0.x); fma2(acc2[0][1], p0.x, q0.y);
        fma2(acc2[0][2], p0.x, q1.x); fma2(acc2[0][3], p0.x, q1.y);
        fma2(acc2[1][0], p0.y, q0.x); fma2(acc2[1][1], p0.y, q0.y);
        fma2(acc2[1][2], p0.y, q1.x); fma2(acc2[1][3], p0.y, q1.y);
        fma2(acc2[2][0], p1.x, q0.x); fma2(acc2[2][1], p1.x, q0.y);
        fma2(acc2[2][2], p1.x, q1.x); fma2(acc2[2][3], p1.x, q1.y);
        fma2(acc2[3][0], p1.y, q0.x); fma2(acc2[3][1], p1.y, q0.y);
        fma2(acc2[3][2], p1.y, q1.x); fma2(acc2[3][3], p1.y, q1.y);
        fma2(acc2[4][0], p2.x, q0.x); fma2(acc2[4][1], p2.x, q0.y);
        fma2(acc2[4][2], p2.x, q1.x); fma2(acc2[4][3], p2.x, q1.y);
        fma2(acc2[5][0], p2.y, q0.x); fma2(acc2[5][1], p2.y, q0.y);
        fma2(acc2[5][2], p2.y, q1.x); fma2(acc2[5][3], p2.y, q1.y);
        fma2(acc2[6][0], p3.x, q0.x); fma2(acc2[6][1], p3.x, q0.y);
        fma2(acc2[6][2], p3.x, q1.x); fma2(acc2[6][3], p3.x, q1.y);
        fma2(acc2[7][0], p3.y, q0.x); fma2(acc2[7][1], p3.y, q0.y);
        fma2(acc2[7][2], p3.y, q1.x); fma2(acc2[7][3], p3.y, q1.y);
    }
}

__device__ __forceinline__ void stage_tile(
    float (&Asb)[8][256], float (&Bsb)[8][128],
    const float4& a4, const float4& b4,
    int aRow, int aCol, int bRow, int bCol)
{
    *(unsigned long long*)&Asb[aCol + 0][2 * aRow] = pack2(a4.x);
    *(unsigned long long*)&Asb[aCol + 1][2 * aRow] = pack2(a4.y);
    *(unsigned long long*)&Asb[aCol + 2][2 * aRow] = pack2(a4.z);
    *(unsigned long long*)&Asb[aCol + 3][2 * aRow] = pack2(a4.w);
    *(float4*)&Bsb[bRow][bCol] = b4;
}

// ---------------------------------------------------------------------------
// K1: z1 = seq @ W1[l] + b1[l].  UNCHANGED (128x128x8 FFMA2 tiles).
// grid = (6, 4, 32), 256 threads.
// ---------------------------------------------------------------------------
__global__ __launch_bounds__(256, 2) void gemm1_kernel(
    const float* __restrict__ seq, const float* __restrict__ W1,
    const float* __restrict__ b1, const int* __restrict__ lang)
{
    __shared__ float As0[8][256], As1[8][256];
    __shared__ float Bs0[8][128], Bs1[8][128];

    const int b = blockIdx.z;
    const int l = lang[b];
    const int tid = threadIdx.x;

    const int aRow = tid >> 1;
    const int aCol = (tid & 1) << 2;
    const int bRow = tid >> 5;
    const int bCol = (tid & 31) << 2;

    const float* Aptr = seq + ((size_t)b * SS + blockIdx.y * 128 + aRow) * HH + aCol;
    const float* Bptr = W1 + (size_t)l * HH * HH + (size_t)bRow * HH
                        + blockIdx.x * 128 + bCol;

    stage_tile(As0, Bs0, *(const float4*)Aptr, *(const float4*)Bptr,
               aRow, aCol, bRow, bCol);
    __syncthreads();

    unsigned long long acc2[8][4] = {};
    const int tx = tid & 15;
    const int ty = tid >> 4;

    const int NKT = HH / 8;    // 96 (even)
    #pragma unroll 1
    for (int kt = 0; kt < NKT; kt += 2) {
        {
            float4 na4 = *(const float4*)(Aptr + (kt + 1) * 8);
            float4 nb4 = *(const float4*)(Bptr + (size_t)(kt + 1) * 8 * HH);
            mma_ktile(As0, Bs0, acc2, tx, ty);
            stage_tile(As1, Bs1, na4, nb4, aRow, aCol, bRow, bCol);
        }
        __syncthreads();
        {
            float4 na4, nb4;
            const bool more = (kt + 2) < NKT;
            if (more) {
                na4 = *(const float4*)(Aptr + (kt + 2) * 8);
                nb4 = *(const float4*)(Bptr + (size_t)(kt + 2) * 8 * HH);
            }
            mma_ktile(As1, Bs1, acc2, tx, ty);
            if (more)
                stage_tile(As0, Bs0, na4, nb4, aRow, aCol, bRow, bCol);
        }
        __syncthreads();
    }

    const int d0 = blockIdx.x * 128;
    const float* bias = b1 + l * HH + d0;
    float4 bv0 = *(const float4*)(bias + tx * 4);
    float4 bv1 = *(const float4*)(bias + tx * 4 + 64);
    float* C = g_z1 + ((size_t)b * SS + blockIdx.y * 128) * HH + d0;

    #pragma unroll
    for (int i = 0; i < 8; i++) {
        int m = (i < 4) ? (ty * 4 + i) : (64 + ty * 4 + (i - 4));
        float4 o0, o1;
        o0.x = lo32(acc2[i][0]) + bv0.x;
        o0.y = hi32(acc2[i][0]) + bv0.y;
        o0.z = lo32(acc2[i][1]) + bv0.z;
        o0.w = hi32(acc2[i][1]) + bv0.w;
        o1.x = lo32(acc2[i][2]) + bv1.x;
        o1.y = hi32(acc2[i][2]) + bv1.y;
        o1.z = lo32(acc2[i][3]) + bv1.z;
        o1.w = hi32(acc2[i][3]) + bv1.w;
        *(float4*)(C + (size_t)m * HH + tx * 4)      = o0;
        *(float4*)(C + (size_t)m * HH + tx * 4 + 64) = o1;
    }
}

// ---------------------------------------------------------------------------
// K2: LN+ReLU+masked-sum over 64-row chunks. UNCHANGED.
// grid = (8, 32), 256 threads.
// ---------------------------------------------------------------------------
__global__ __launch_bounds__(256) void ln_pool_kernel(
    const float* __restrict__ gam, const float* __restrict__ bet,
    const int* __restrict__ lang, const float* __restrict__ mask)
{
    const int b = blockIdx.y, chunk = blockIdx.x;
    const int l = lang[b];
    const int warp = threadIdx.x >> 5, lane = threadIdx.x & 31;

    float4 gv[6], bev[6], accp[6];
    #pragma unroll
    for (int j = 0; j < 6; j++) {
        int c = lane * 4 + 128 * j;
        gv[j]  = *(const float4*)&gam[l * HH + c];
        bev[j] = *(const float4*)&bet[l * HH + c];
        accp[j] = make_float4(0.f, 0.f, 0.f, 0.f);
    }

    for (int i = 0; i < 8; i++) {
        int r = chunk * 64 + warp * 8 + i;
        const float* row = g_z1 + ((size_t)b * SS + r) * HH;
        float4 v[6];
        float s1 = 0.f, s2 = 0.f;
        #pragma unroll
        for (int j = 0; j < 6; j++) {
            float4 x = *(const float4*)&row[lane * 4 + 128 * j];
            v[j] = x;
            s1 += x.x + x.y + x.z + x.w;
            s2 += x.x * x.x + x.y * x.y + x.z * x.z + x.w * x.w;
        }
        #pragma unroll
        for (int o = 16; o > 0; o >>= 1) {
            s1 += __shfl_xor_sync(0xffffffffu, s1, o);
            s2 += __shfl_xor_sync(0xffffffffu, s2, o);
        }
        float mean = s1 * (1.0f / HH);
        float var  = s2 * (1.0f / HH) - mean * mean;
        float inv  = rsqrtf(var + 1e-5f);
        float mwt  = mask[b * SS + r];
        #pragma unroll
        for (int j = 0; j < 6; j++) {
            accp[j].x += mwt * fmaxf((v[j].x - mean) * inv * gv[j].x + bev[j].x, 0.f);
            accp[j].y += mwt * fmaxf((v[j].y - mean) * inv * gv[j].y + bev[j].y, 0.f);
            accp[j].z += mwt * fmaxf((v[j].z - mean) * inv * gv[j].z + bev[j].z, 0.f);
            accp[j].w += mwt * fmaxf((v[j].w - mean) * inv * gv[j].w + bev[j].w, 0.f);
        }
    }

    __shared__ float sm[8][HH];
    #pragma unroll
    for (int j = 0; j < 6; j++)
        *(float4*)&sm[warp][lane * 4 + 128 * j] = accp[j];
    __syncthreads();
    for (int c = threadIdx.x; c < HH; c += 256) {
        float s = 0.f;
        #pragma unroll
        for (int w = 0; w < 8; w++) s += sm[w][c];
        g_parts[((size_t)chunk * BB + b) * HH + c] = s;
    }
}

// ---------------------------------------------------------------------------
// K3a: ph[b,:] = (sum of g_parts chunks) / (msum+eps);  msfac[b] = msum/(msum+eps)
// grid = 32, 768 threads.
// ---------------------------------------------------------------------------
__global__ __launch_bounds__(768) void pool_ph_kernel(const float* __restrict__ mask)
{
    const int b = blockIdx.x, tid = threadIdx.x;
    const int warp = tid >> 5, lane = tid & 31;
    __shared__ float swarp[24];
    __shared__ float sinvd, sfac;

    float ms = (tid < SS) ? mask[b * SS + tid] : 0.f;
    #pragma unroll
    for (int o = 16; o > 0; o >>= 1) ms += __shfl_xor_sync(0xffffffffu, ms, o);
    if (lane == 0) swarp[warp] = ms;
    __syncthreads();
    if (tid == 0) {
        float t = 0.f;
        #pragma unroll
        for (int w = 0; w < 24; w++) t += swarp[w];
        float invd = 1.0f / (t + 1e-10f);
        sinvd = invd;
        sfac  = t * invd;
    }
    __syncthreads();

    const float invd = sinvd;
    float s = 0.f;
    #pragma unroll
    for (int ch = 0; ch < 8; ch++)
        s += g_parts[((size_t)ch * BB + b) * HH + tid];
    g_ph[b * HH + tid] = s * invd;
    if (tid == 0) g_msfac[b] = sfac;
}

// ---------------------------------------------------------------------------
// K3b: gemm2 partials — block (q,b) reduces a 128-row chunk of W2[l] over all
// 768 columns with coalesced float4 loads. grid = (6, 32), 768 threads.
// thread: col4 = (tid%192)*4, rowgroup r = tid/192 (rows r+4j within chunk).
// ---------------------------------------------------------------------------
__global__ __launch_bounds__(768) void gemm2_partial_kernel(
    const int* __restrict__ lang, const float* __restrict__ W2)
{
    const int q = blockIdx.x, b = blockIdx.y, tid = threadIdx.x;
    const int l = lang[b];
    __shared__ float ph_s[HH];
    __shared__ float sm2[4][HH];

    ph_s[tid] = g_ph[b * HH + tid];
    __syncthreads();

    const int col = (tid % 192) * 4;
    const int r   = tid / 192;          // 0..3
    const float* W = W2 + (size_t)l * HH * HH;

    float4 acc = make_float4(0.f, 0.f, 0.f, 0.f);
    #pragma unroll
    for (int j = 0; j < 32; j++) {
        int i = q * 128 + r + 4 * j;
        float4 wv = *(const float4*)&W[(size_t)i * HH + col];
        float p = ph_s[i];
        acc.x += p * wv.x; acc.y += p * wv.y;
        acc.z += p * wv.z; acc.w += p * wv.w;
    }
    *(float4*)&sm2[r][col] = acc;
    __syncthreads();
    g_p2[((size_t)q * BB + b) * HH + tid] =
        sm2[0][tid] + sm2[1][tid] + sm2[2][tid] + sm2[3][tid];
}

// ---------------------------------------------------------------------------
// K3c: pooled[b,d] = sum_q p2[q,b,d] + b2[l,d]*msfac[b].  grid = 32, 768 thr.
// ---------------------------------------------------------------------------
__global__ __launch_bounds__(768) void pool_combine_kernel(
    const int* __restrict__ lang, const float* __restrict__ b2)
{
    const int b = blockIdx.x, d = threadIdx.x;
    const int l = lang[b];
    float s = 0.f;
    #pragma unroll
    for (int q = 0; q < 6; q++) s += g_p2[((size_t)q * BB + b) * HH + d];
    g_pooled[b * HH + d] = s + b2[l * HH + d] * g_msfac[b];
}

// ---------------------------------------------------------------------------
// K4a: fuse partials — block (q,b) reduces a 124-row chunk of Wf over all 512
// columns with coalesced float4 loads. grid = (7, 32), 512 threads.
// 868 = 7*124. thread: col4 = (tid%128)*4, rowgroup r = tid/128.
// ---------------------------------------------------------------------------
__global__ __launch_bounds__(512) void fuse_partial_kernel(
    const float* __restrict__ lda, const float* __restrict__ Wf)
{
    const int q = blockIdx.x, b = blockIdx.y, tid = threadIdx.x;
    __shared__ float comb[HH + TT];
    __shared__ float smf[4][THH];

    for (int i = tid; i < HH; i += 512) comb[i] = g_pooled[b * HH + i];
    for (int i = tid; i < TT; i += 512) comb[HH + i] = lda[b * TT + i];
    __syncthreads();

    const int col = (tid % 128) * 4;
    const int r   = tid / 128;          // 0..3

    float4 acc = make_float4(0.f, 0.f, 0.f, 0.f);
    #pragma unroll
    for (int j = 0; j < 31; j++) {
        int i = q * 124 + r + 4 * j;    // covers q*124 .. q*124+123
        float4 wv = *(const float4*)&Wf[(size_t)i * THH + col];
        float p = comb[i];
        acc.x += p * wv.x; acc.y += p * wv.y;
        acc.z += p * wv.z; acc.w += p * wv.w;
    }
    *(float4*)&smf[r][col] = acc;
    __syncthreads();
    g_fp[((size_t)q * BB + b) * THH + tid] =
        smf[0][tid] + smf[1][tid] + smf[2][tid] + smf[3][tid];
}

// ---------------------------------------------------------------------------
// K4b: accf = bf + sum_q fp; LN over 512; ReLU. grid = 32, 512 threads.
// ---------------------------------------------------------------------------
__global__ __launch_bounds__(512) void fuse_ln_kernel(
    const float* __restrict__ bf, const float* __restrict__ gf,
    const float* __restrict__ bef, float* __restrict__ out)
{
    const int b = blockIdx.x, d = threadIdx.x;
    __shared__ float sr1[16], sr2[16];

    float accf = bf[d];
    #pragma unroll
    for (int q = 0; q < 7; q++) accf += g_fp[((size_t)q * BB + b) * THH + d];

    float s1 = accf, s2 = accf * accf;
    #pragma unroll
    for (int o = 16; o > 0; o >>= 1) {
        s1 += __shfl_xor_sync(0xffffffffu, s1, o);
        s2 += __shfl_xor_sync(0xffffffffu, s2, o);
    }
    const int warp = d >> 5, lane = d & 31;
    if (lane == 0) { sr1[warp] = s1; sr2[warp] = s2; }
    __syncthreads();
    if (warp == 0) {
        float t1 = (lane < 16) ? sr1[lane] : 0.f;
        float t2 = (lane < 16) ? sr2[lane] : 0.f;
        #pragma unroll
        for (int o = 16; o > 0; o >>= 1) {
            t1 += __shfl_xor_sync(0xffffffffu, t1, o);
            t2 += __shfl_xor_sync(0xffffffffu, t2, o);
        }
        if (lane == 0) { sr1[0] = t1; sr2[0] = t2; }
    }
    __syncthreads();
    float mean = sr1[0] * (1.0f / THH);
    float var  = sr2[0] * (1.0f / THH) - mean * mean;
    float inv  = rsqrtf(var + 1e-5f);
    float t = (accf - mean) * inv * gf[d] + bef[d];
    out[b * THH + d] = fmaxf(t, 0.f);
}

// ---------------------------------------------------------------------------
extern "C" void kernel_launch(void* const* d_in, const int* in_sizes, int n_in,
                              void* d_out, int out_size)
{
    const float* seq  = (const float*)d_in[0];
    const float* mask = (const float*)d_in[1];
    const int*   lang = (const int*)  d_in[2];
    const float* lda  = (const float*)d_in[3];
    const float* W1   = (const float*)d_in[4];
    const float* b1   = (const float*)d_in[5];
    const float* gam1 = (const float*)d_in[6];
    const float* bet1 = (const float*)d_in[7];
    const float* W2   = (const float*)d_in[8];
    const float* b2   = (const float*)d_in[9];
    const float* Wf   = (const float*)d_in[10];
    const float* bfv  = (const float*)d_in[11];
    const float* gfv  = (const float*)d_in[12];
    const float* befv = (const float*)d_in[13];
    float* out = (float*)d_out;

    dim3 grid1(HH / 128, SS / 128, BB);      // (6, 4, 32)
    gemm1_kernel<<<grid1, 256>>>(seq, W1, b1, lang);

    dim3 grid2(8, BB);
    ln_pool_kernel<<<grid2, 256>>>(gam1, bet1, lang, mask);

    pool_ph_kernel<<<BB, 768>>>(mask);

    dim3 grid3(6, BB);
    gemm2_partial_kernel<<<grid3, 768>>>(lang, W2);

    pool_combine_kernel<<<BB, 768>>>(lang, b2);

    dim3 grid4(7, BB);
    fuse_partial_kernel<<<grid4, 512>>>(lda, Wf);

    fuse_ln_kernel<<<BB, 512>>>(bfv, gfv, befv, out);
}